// round 7
// baseline (speedup 1.0000x reference)
#include <cuda_runtime.h>
#include <math.h>
#include <stdint.h>

#define CDIV(a,b) (((a)+(b)-1)/(b))
#define B_   64
#define L_   20
#define H_   300
#define P_   8
#define N_   32768
#define E_   262144
#define C_   2048
#define OUT_ 1845
#define LDSIM 2052

typedef unsigned long long u64;

__device__ __align__(16) float g_qt[B_*L_*H_];
__device__ __align__(16) float g_sim[B_*L_*LDSIM];
__device__ __align__(16) float g_vextT[H_*LDSIM];
__device__ __align__(16) float g_tagged[B_*L_*H_];
__device__ __align__(16) float g_Zx[B_*L_*1200];
__device__ __align__(16) float g_h[B_*H_];
__device__ __align__(16) float g_hidden[B_*4*H_];
__device__ __align__(16) float g_instr[B_*4*H_];
__device__ __align__(16) float g_npsim[B_*P_];
__device__ __align__(16) float g_rsim[B_];
__device__ __align__(16) float g_dist[N_];
__device__ __align__(16) float g_dotns[N_];
__device__ __align__(16) float g_dotnr[N_];
__device__ __align__(16) float g_agg[B_*H_];
__device__ __align__(16) float g_WihT[H_*1200];
__device__ __align__(16) float g_WhhT[H_*1200];
__device__ __align__(16) float g_rWihT[H_*H_];
__device__ __align__(16) float g_rWhhT[H_*H_];
__device__ __align__(16) float g_fc1T[600*600];
__device__ __align__(16) float g_fc2T[600*OUT_];
__device__ int g_count[B_];

__device__ __forceinline__ float sigm(float x){ return 1.f/(1.f+expf(-x)); }
__device__ __forceinline__ float eluf(float x){ return x>0.f ? x : expm1f(x); }

__device__ __forceinline__ void ffma2(u64& d, u64 a, u64 b){
    asm("fma.rn.f32x2 %0, %1, %2, %0;" : "+l"(d) : "l"(a), "l"(b));
}
union F2U { u64 u; float2 f; };

// ---------------- packed-f32x2 SGEMM 128x128x16, fused epilogues ----------------
// MODE 0: C = A@B (+=C if ACC).  MODE 2: node fused.  MODE 3: edge fused.
// thread (tx,ty): rows ty*8+{0..7} (as 4 adjacent pairs), cols tx+16j (j=0..7)
template<int MODE, bool ACC>
__global__ void __launch_bounds__(256)
sgemm2_k(const float* __restrict__ A, int lda,
         const float* __restrict__ Bm, int ldb,
         float* __restrict__ Cm, int ldc, int Nc, int K,
         const int* __restrict__ batchOf,
         const float* __restrict__ npsim, const float* __restrict__ instrP,
         const float* __restrict__ wvec, float* __restrict__ dotOut,
         const int* __restrict__ srcI, const int* __restrict__ dstI,
         const float* __restrict__ distP)
{
    __shared__ __align__(16) float As[16][128];
    __shared__ __align__(16) float Bs2[16][256];
    constexpr int SC = (MODE==2) ? 2400 : ((MODE==3) ? 304 : 4);
    __shared__ float s_sc[SC];
    const int tid = threadIdx.x;
    const int row0 = blockIdx.y * 128, col0 = blockIdx.x * 128;
    const int tx = tid & 15, ty = tid >> 4;

    if (MODE==2){
        int b = batchOf[row0];
        for (int j=tid; j<2400; j+=256){
            int p = j/300, h = j - p*300;
            s_sc[j] = npsim[b*8+p]*instrP[(size_t)b*1200+h];
        }
    }
    if (MODE==3){
        int b = batchOf[row0];
        for (int j=tid; j<300; j+=256) s_sc[j] = instrP[(size_t)b*1200+j];
    }
    if (MODE==2||MODE==3) __syncthreads();

    u64 acc[4][8];
    #pragma unroll
    for(int p=0;p<4;p++){
        #pragma unroll
        for(int j=0;j<8;j++) acc[p][j]=0ull;
    }

    for (int k0=0; k0<K; k0+=16){
        // stage global loads in regs
        float4 av[2], bv[2];
        int ar[2], aq[2], bk[2], bc[2];
        #pragma unroll
        for (int l=0;l<2;l++){
            int idx = tid + l*256;
            ar[l] = idx>>2; aq[l] = idx&3;
            int k = k0 + aq[l]*4;
            av[l] = make_float4(0.f,0.f,0.f,0.f);
            if (k < K)
                av[l] = *reinterpret_cast<const float4*>(A + (size_t)(row0+ar[l])*lda + k);
            if (MODE==2){
                av[l].x *= s_sc[k]; av[l].y *= s_sc[k+1];
                av[l].z *= s_sc[k+2]; av[l].w *= s_sc[k+3];
            }
            bk[l] = idx>>5; bc[l] = (idx&31)*4;
            int krow = k0 + bk[l];
            bv[l] = make_float4(0.f,0.f,0.f,0.f);
            if (krow < K){
                int c = col0 + bc[l];
                const float* bp = Bm + (size_t)krow*ldb;
                if (c + 3 < Nc) bv[l] = *reinterpret_cast<const float4*>(bp + c);
                else {
                    if (c  <Nc) bv[l].x = bp[c];
                    if (c+1<Nc) bv[l].y = bp[c+1];
                    if (c+2<Nc) bv[l].z = bp[c+2];
                    if (c+3<Nc) bv[l].w = bp[c+3];
                }
                if (MODE==3){ float s=s_sc[krow]; bv[l].x*=s; bv[l].y*=s; bv[l].z*=s; bv[l].w*=s; }
            }
        }
        __syncthreads();
        #pragma unroll
        for (int l=0;l<2;l++){
            As[aq[l]*4+0][ar[l]]=av[l].x; As[aq[l]*4+1][ar[l]]=av[l].y;
            As[aq[l]*4+2][ar[l]]=av[l].z; As[aq[l]*4+3][ar[l]]=av[l].w;
            float4 lo = make_float4(bv[l].x, bv[l].x, bv[l].y, bv[l].y);
            float4 hi = make_float4(bv[l].z, bv[l].z, bv[l].w, bv[l].w);
            *reinterpret_cast<float4*>(&Bs2[bk[l]][bc[l]*2])   = lo;
            *reinterpret_cast<float4*>(&Bs2[bk[l]][bc[l]*2+4]) = hi;
        }
        __syncthreads();
        #pragma unroll
        for (int kk=0;kk<16;kk++){
            u64 aP[4], bP[8];
            #pragma unroll
            for(int p=0;p<4;p++) aP[p] = *reinterpret_cast<const u64*>(&As[kk][ty*8+2*p]);
            #pragma unroll
            for(int j=0;j<8;j++) bP[j] = *reinterpret_cast<const u64*>(&Bs2[kk][(tx+16*j)*2]);
            #pragma unroll
            for(int p=0;p<4;p++){
                #pragma unroll
                for(int j=0;j<8;j++) ffma2(acc[p][j], aP[p], bP[j]);
            }
        }
    }

    if (MODE==0){
        #pragma unroll
        for(int p=0;p<4;p++){
            int r0 = row0 + ty*8 + 2*p;
            #pragma unroll
            for(int j=0;j<8;j++){
                int c = col0 + tx + 16*j;
                if (c < Nc){
                    F2U v; v.u = acc[p][j];
                    size_t i0 = (size_t)r0*ldc + c;
                    size_t i1 = (size_t)(r0+1)*ldc + c;
                    Cm[i0] = ACC ? (Cm[i0] + v.f.x) : v.f.x;
                    Cm[i1] = ACC ? (Cm[i1] + v.f.y) : v.f.y;
                }
            }
        }
    } else {
        float wv[8];
        #pragma unroll
        for(int j=0;j<8;j++){
            int c = col0 + tx + 16*j;
            wv[j] = (c<Nc) ? wvec[c] : 0.f;
        }
        #pragma unroll
        for(int p=0;p<4;p++){
            float sL=0.f, sH=0.f;
            #pragma unroll
            for(int j=0;j<8;j++){
                F2U v; v.u = acc[p][j];
                float lo = v.f.x, hi = v.f.y;
                lo = lo>0.f?lo:expm1f(lo);
                hi = hi>0.f?hi:expm1f(hi);
                sL += lo*wv[j]; sH += hi*wv[j];
            }
            #pragma unroll
            for (int m=1;m<16;m<<=1){
                sL += __shfl_xor_sync(0xffffffffu, sL, m);
                sH += __shfl_xor_sync(0xffffffffu, sH, m);
            }
            if (tx==0){
                int r0 = row0 + ty*8 + 2*p;
                if (MODE==2){
                    atomicAdd(&dotOut[r0],   sL);
                    atomicAdd(&dotOut[r0+1], sH);
                } else {
                    atomicAdd(&dotOut[dstI[r0]],   distP[srcI[r0]]*sL);
                    atomicAdd(&dotOut[dstI[r0+1]], distP[srcI[r0+1]]*sH);
                }
            }
        }
    }
}

// ---------------- small kernels ----------------
__global__ void transpose_k(const float* __restrict__ src, float* __restrict__ dst, int R, int Cc){
    int idx = blockIdx.x*blockDim.x + threadIdx.x;
    if (idx < R*Cc){ int r=idx/Cc, c=idx-r*Cc; dst[(size_t)c*R + r] = src[idx]; }
}
__global__ void vextT_k(const float* __restrict__ cv, const float* __restrict__ demb){
    int idx = blockIdx.x*blockDim.x + threadIdx.x;
    if (idx < H_*LDSIM){
        int h = idx / LDSIM, c = idx - h*LDSIM;
        float v = 0.f;
        if (c < C_) v = cv[(size_t)c*H_ + h];
        else if (c == C_) v = demb[h];
        g_vextT[idx] = v;
    }
}
__global__ void __launch_bounds__(256) smrow_k(){
    __shared__ float red[256];
    int r = blockIdx.x, t = threadIdx.x;
    float* row = g_sim + (size_t)r*LDSIM;
    float mx = -1e30f;
    for(int c=t;c<2049;c+=256) mx = fmaxf(mx, row[c]);
    red[t]=mx; __syncthreads();
    for(int s=128;s>0;s>>=1){ if(t<s) red[t]=fmaxf(red[t],red[t+s]); __syncthreads(); }
    mx = red[0]; __syncthreads();
    float sm = 0.f;
    for(int c=t;c<2049;c+=256){ float e=expf(row[c]-mx); row[c]=e; sm+=e; }
    red[t]=sm; __syncthreads();
    for(int s=128;s>0;s>>=1){ if(t<s) red[t]+=red[t+s]; __syncthreads(); }
    float inv = 1.f/red[0]; __syncthreads();
    for(int c=t;c<2049;c+=256) row[c]*=inv;
}
__global__ void tagged_init_k(const float* __restrict__ q){
    int idx = blockIdx.x*blockDim.x + threadIdx.x;
    if (idx < B_*L_*H_){
        int r = idx / H_;
        g_tagged[idx] = g_sim[(size_t)r*LDSIM + C_] * q[idx];
    }
}
__global__ void __launch_bounds__(320) lstm_k(const float* __restrict__ bih, const float* __restrict__ bhh){
    __shared__ float h_s[304], c_s[304], z_s[1200];
    int b = blockIdx.x, tid = threadIdx.x;
    if (tid<300){ h_s[tid]=0.f; c_s[tid]=0.f; }
    __syncthreads();
    const float4* W = reinterpret_cast<const float4*>(g_WhhT);
    for (int t=0;t<20;t++){
        if (tid<300){
            int j4 = tid*4;
            float4 a = *reinterpret_cast<const float4*>(&g_Zx[((size_t)b*20+t)*1200 + j4]);
            a.x += bih[j4]+bhh[j4];     a.y += bih[j4+1]+bhh[j4+1];
            a.z += bih[j4+2]+bhh[j4+2]; a.w += bih[j4+3]+bhh[j4+3];
            for(int h=0;h<300;h++){
                float hv = h_s[h];
                float4 w = W[(size_t)h*300 + tid];
                a.x += hv*w.x; a.y += hv*w.y; a.z += hv*w.z; a.w += hv*w.w;
            }
            *reinterpret_cast<float4*>(&z_s[j4]) = a;
        }
        __syncthreads();
        if (tid<300){
            float iv=sigm(z_s[tid]), fv=sigm(z_s[300+tid]);
            float gv=tanhf(z_s[600+tid]), ov=sigm(z_s[900+tid]);
            float c = fv*c_s[tid] + iv*gv;
            c_s[tid]=c; h_s[tid]=ov*tanhf(c);
        }
        __syncthreads();
    }
    if (tid<300) g_h[b*300+tid] = h_s[tid];
}
__global__ void __launch_bounds__(320) rnn_k(const float* __restrict__ rbih, const float* __restrict__ rbhh){
    __shared__ float enc[304], ex[304], hx[304], hn[304];
    int b = blockIdx.x, tid = threadIdx.x;
    if (tid<300) enc[tid]=g_h[b*300+tid];
    __syncthreads();
    if (tid<300){
        float a = rbih[tid]+rbhh[tid];
        for(int k=0;k<300;k++) a += enc[k]*g_rWihT[k*300+tid];
        ex[tid]=a; hx[tid]=0.f;
    }
    __syncthreads();
    for(int it=0; it<4; it++){
        if (tid<300){
            float a = ex[tid];
            for(int k=0;k<300;k++) a += hx[k]*g_rWhhT[k*300+tid];
            a = a>0.f ? a : 0.f;
            hn[tid]=a;
            g_hidden[(size_t)b*1200 + it*300 + tid] = a;
        }
        __syncthreads();
        if (tid<300) hx[tid]=hn[tid];
        __syncthreads();
    }
}
__global__ void __launch_bounds__(256) attn_k(){
    __shared__ float hid[1200], tg[6000], at[80];
    int b = blockIdx.x, tid = threadIdx.x;
    for(int j=tid;j<1200;j+=256) hid[j]=g_hidden[(size_t)b*1200+j];
    for(int j=tid;j<6000;j+=256) tg[j]=g_tagged[(size_t)b*6000+j];
    __syncthreads();
    if (tid<80){
        int i=tid/20, l=tid%20;
        float a=0.f;
        for(int h=0;h<300;h++) a += hid[i*300+h]*tg[l*300+h];
        at[tid]=a;
    }
    __syncthreads();
    if (tid<4){
        float mx=-1e30f;
        for(int l=0;l<20;l++) mx=fmaxf(mx,at[tid*20+l]);
        float s=0.f;
        for(int l=0;l<20;l++){ float e=expf(at[tid*20+l]-mx); at[tid*20+l]=e; s+=e; }
        float inv=1.f/s;
        for(int l=0;l<20;l++) at[tid*20+l]*=inv;
    }
    __syncthreads();
    for(int idx=tid; idx<1200; idx+=256){
        int i=idx/300, h=idx-i*300;
        float a=0.f;
        for(int l=0;l<20;l++) a += at[i*20+l]*tg[l*300+h];
        g_instr[(size_t)b*1200+idx]=a;
    }
}
__global__ void psim_k(const float* __restrict__ pe, int step){
    __shared__ float lg[64][9];
    int tid = threadIdx.x;
    if (tid < 576){
        int b=tid/9, j=tid-b*9;
        const float* ip = g_instr + (size_t)b*1200 + step*300;
        float a=0.f;
        for(int h=0;h<300;h++) a += ip[h]*pe[j*300+h];
        lg[b][j]=a;
    }
    __syncthreads();
    if (tid < 64){
        float mx=-1e30f;
        for(int j=0;j<9;j++) mx=fmaxf(mx,lg[tid][j]);
        float e[9], s=0.f;
        for(int j=0;j<9;j++){ e[j]=expf(lg[tid][j]-mx); s+=e[j]; }
        float inv=1.f/s;
        for(int p=0;p<8;p++) g_npsim[tid*8+p]=e[p]*inv;
        g_rsim[tid]=e[8]*inv;
    }
}
__global__ void zero_misc_k(){
    int idx = blockIdx.x*blockDim.x + threadIdx.x;
    if (idx < B_) g_count[idx]=0;
    if (idx < B_*H_) g_agg[idx]=0.f;
}
__global__ void count_k(const int* __restrict__ ni){
    int n = blockIdx.x*blockDim.x + threadIdx.x;
    if (n < N_) atomicAdd(&g_count[ni[n]], 1);
}
__global__ void distinit_k(const int* __restrict__ ni){
    int n = blockIdx.x*blockDim.x + threadIdx.x;
    if (n < N_) g_dist[n] = 1.f/(float)g_count[ni[n]];
}
__global__ void zerodots_k(){
    int n = blockIdx.x*blockDim.x + threadIdx.x;
    if (n < N_){ g_dotns[n]=0.f; g_dotnr[n]=0.f; }
}
__global__ void __launch_bounds__(512) segsm_k(){
    __shared__ float red[512];
    int b = blockIdx.x, t = threadIdx.x;
    int n = b*512 + t;
    float v1 = g_dotns[n], v2 = g_dotnr[n];
    red[t]=v1; __syncthreads();
    for(int s=256;s>0;s>>=1){ if(t<s) red[t]=fmaxf(red[t],red[t+s]); __syncthreads(); }
    float m1=red[0]; __syncthreads();
    float e1=expf(v1-m1);
    red[t]=e1; __syncthreads();
    for(int s=256;s>0;s>>=1){ if(t<s) red[t]+=red[t+s]; __syncthreads(); }
    float s1=red[0]; __syncthreads();
    red[t]=v2; __syncthreads();
    for(int s=256;s>0;s>>=1){ if(t<s) red[t]=fmaxf(red[t],red[t+s]); __syncthreads(); }
    float m2=red[0]; __syncthreads();
    float e2=expf(v2-m2);
    red[t]=e2; __syncthreads();
    for(int s=256;s>0;s>>=1){ if(t<s) red[t]+=red[t+s]; __syncthreads(); }
    float s2=red[0];
    float rs = g_rsim[b];
    g_dist[n] = rs*(e2/s2) + (1.f-rs)*(e1/s1);
}
__global__ void __launch_bounds__(320) agg_k(const float* __restrict__ attrs, const int* __restrict__ ni){
    __shared__ float np_s[8], d_s[64];
    int blk = blockIdx.x, tid = threadIdx.x;
    int n0 = blk*64;
    int b = ni[n0];
    if (tid<8)  np_s[tid] = g_npsim[b*8+tid];
    if (tid<64) d_s[tid]  = g_dist[n0+tid];
    __syncthreads();
    if (tid<300){
        float acc = 0.f;
        for(int n=0;n<64;n++){
            const float* ap = attrs + (size_t)(n0+n)*2400 + tid;
            float s = 0.f;
            #pragma unroll
            for(int p=0;p<8;p++) s += np_s[p]*ap[p*300];
            acc += d_s[n]*s;
        }
        atomicAdd(&g_agg[b*300+tid], acc);
    }
}
__global__ void __launch_bounds__(256) fc_k(const float* __restrict__ fc1b,
                                            const float* __restrict__ fc2b,
                                            float* __restrict__ out){
    __shared__ float ft[600], h1[600];
    int b = blockIdx.x, tid = threadIdx.x;
    for(int j=tid;j<300;j+=256){ ft[j]=g_h[b*300+j]; ft[300+j]=g_agg[b*300+j]; }
    __syncthreads();
    for(int j=tid;j<600;j+=256){
        float a = fc1b[j];
        for(int k=0;k<600;k++) a += ft[k]*g_fc1T[k*600+j];
        h1[j] = eluf(a);
    }
    __syncthreads();
    for(int o=tid;o<OUT_;o+=256){
        float a = fc2b[o];
        for(int k=0;k<600;k++) a += h1[k]*g_fc2T[(size_t)k*OUT_+o];
        out[(size_t)b*OUT_+o]=a;
    }
}

// ---------------- driver ----------------
extern "C" void kernel_launch(void* const* d_in, const int* in_sizes, int n_in,
                              void* d_out, int out_size) {
    const float* questions = (const float*)d_in[0];
    const float* cv        = (const float*)d_in[1];
    const float* pe        = (const float*)d_in[2];
    const float* attrs     = (const float*)d_in[3];
    const float* eattrs    = (const float*)d_in[4];
    const float* wtag      = (const float*)d_in[5];
    const float* demb      = (const float*)d_in[6];
    const float* lWih      = (const float*)d_in[7];
    const float* lWhh      = (const float*)d_in[8];
    const float* lbih      = (const float*)d_in[9];
    const float* lbhh      = (const float*)d_in[10];
    const float* rWih      = (const float*)d_in[11];
    const float* rWhh      = (const float*)d_in[12];
    const float* rbih      = (const float*)d_in[13];
    const float* rbhh      = (const float*)d_in[14];
    const float* Wp        = (const float*)d_in[15];
    const float* We        = (const float*)d_in[16];
    const float* w_ns      = (const float*)d_in[17];
    const float* w_rs      = (const float*)d_in[18];
    const float* fc1w      = (const float*)d_in[19];
    const float* fc1b      = (const float*)d_in[20];
    const float* fc2w      = (const float*)d_in[21];
    const float* fc2b      = (const float*)d_in[22];
    const int*   ni        = (const int*)d_in[23];
    const int*   esrc      = (const int*)d_in[24];
    const int*   edst      = (const int*)d_in[25];
    const int*   ebatch    = (const int*)d_in[26];
    float* out = (float*)d_out;

    float *WihT, *WhhT, *rWihT, *rWhhT, *fc1T, *fc2T;
    float *qt, *sim, *vextT, *tagged, *Zx, *npsimP, *instrP0;
    float *dotns, *dotnr, *distP;
    cudaGetSymbolAddress((void**)&WihT,  g_WihT);
    cudaGetSymbolAddress((void**)&WhhT,  g_WhhT);
    cudaGetSymbolAddress((void**)&rWihT, g_rWihT);
    cudaGetSymbolAddress((void**)&rWhhT, g_rWhhT);
    cudaGetSymbolAddress((void**)&fc1T,  g_fc1T);
    cudaGetSymbolAddress((void**)&fc2T,  g_fc2T);
    cudaGetSymbolAddress((void**)&qt,    g_qt);
    cudaGetSymbolAddress((void**)&sim,   g_sim);
    cudaGetSymbolAddress((void**)&vextT, g_vextT);
    cudaGetSymbolAddress((void**)&tagged,g_tagged);
    cudaGetSymbolAddress((void**)&Zx,    g_Zx);
    cudaGetSymbolAddress((void**)&npsimP,g_npsim);
    cudaGetSymbolAddress((void**)&instrP0,g_instr);
    cudaGetSymbolAddress((void**)&dotns, g_dotns);
    cudaGetSymbolAddress((void**)&dotnr, g_dotnr);
    cudaGetSymbolAddress((void**)&distP, g_dist);

    // transposes / prep
    transpose_k<<<CDIV(1200*300,256),256>>>(lWih, WihT, 1200, 300);
    transpose_k<<<CDIV(1200*300,256),256>>>(lWhh, WhhT, 1200, 300);
    transpose_k<<<CDIV(300*300,256),256>>>(rWih, rWihT, 300, 300);
    transpose_k<<<CDIV(300*300,256),256>>>(rWhh, rWhhT, 300, 300);
    transpose_k<<<CDIV(600*600,256),256>>>(fc1w, fc1T, 600, 600);
    transpose_k<<<CDIV(OUT_*600,256),256>>>(fc2w, fc2T, OUT_, 600);
    vextT_k<<<CDIV(H_*LDSIM,256),256>>>(cv, demb);
    zero_misc_k<<<CDIV(B_*H_,256),256>>>();
    count_k<<<CDIV(N_,256),256>>>(ni);
    distinit_k<<<CDIV(N_,256),256>>>(ni);

    // tagging
    sgemm2_k<0,false><<<dim3(CDIV(300,128),10),256>>>(questions,300, wtag,300, qt,300, 300,300,
        0,0,0,0,0,0,0,0);
    sgemm2_k<0,false><<<dim3(CDIV(2049,128),10),256>>>(qt,300, vextT,LDSIM, sim,LDSIM, 2049,300,
        0,0,0,0,0,0,0,0);
    smrow_k<<<B_*L_,256>>>();
    tagged_init_k<<<CDIV(B_*L_*H_,256),256>>>(questions);
    sgemm2_k<0,true><<<dim3(CDIV(300,128),10),256>>>(sim,LDSIM, cv,300, tagged,300, 300,2048,
        0,0,0,0,0,0,0,0);

    // LSTM + RNN + attn
    sgemm2_k<0,false><<<dim3(CDIV(1200,128),10),256>>>(tagged,300, WihT,1200, Zx,1200, 1200,300,
        0,0,0,0,0,0,0,0);
    lstm_k<<<B_,320>>>(lbih, lbhh);
    rnn_k<<<B_,320>>>(rbih, rbhh);
    attn_k<<<B_,256>>>();

    // reasoning steps
    for (int step=0; step<3; step++){
        psim_k<<<1,576>>>(pe, step);
        zerodots_k<<<CDIV(N_,256),256>>>();
        sgemm2_k<2,false><<<dim3(CDIV(300,128), N_/128),256>>>(attrs,2400, Wp,300,
            (float*)0,0, 300,2400, ni, npsimP, instrP0+step*300, w_ns, dotns, 0,0,0);
        sgemm2_k<3,false><<<dim3(CDIV(300,128), E_/128),256>>>(eattrs,300, We,300,
            (float*)0,0, 300,300, ebatch, 0, instrP0+step*300, w_rs, dotnr, esrc, edst, distP);
        segsm_k<<<B_,512>>>();
    }

    // final aggregation + MLP
    psim_k<<<1,576>>>(pe, 3);
    agg_k<<<N_/64,320>>>(attrs, ni);
    fc_k<<<B_,256>>>(fc1b, fc2b, out);
}

// round 8
// speedup vs baseline: 2.2255x; 2.2255x over previous
#include <cuda_runtime.h>
#include <cuda_bf16.h>
#include <math.h>
#include <stdint.h>

#define CDIV(a,b) (((a)+(b)-1)/(b))
#define B_   64
#define L_   20
#define H_   300
#define P_   8
#define N_   32768
#define E_   262144
#define C_   2048
#define OUT_ 1845
#define LDSIM 2052

#define KPN 2432
#define KPE 320
#define NP  320

// ---------------- scratch ----------------
__device__ __align__(16) float g_qt[B_*L_*H_];
__device__ __align__(16) float g_sim[B_*L_*LDSIM];
__device__ __align__(16) float g_vextT[H_*LDSIM];
__device__ __align__(16) float g_tagged[B_*L_*H_];
__device__ __align__(16) float g_Zx[B_*L_*1200];
__device__ __align__(16) float g_h[B_*H_];
__device__ __align__(16) float g_hidden[B_*4*H_];
__device__ __align__(16) float g_instr[B_*4*H_];
__device__ __align__(16) float g_npsim[B_*P_];
__device__ __align__(16) float g_rsim[B_];
__device__ __align__(16) float g_dist[N_];
__device__ __align__(16) float g_dotns[N_];
__device__ __align__(16) float g_dotnr[N_];
__device__ __align__(16) float g_agg[B_*H_];
__device__ __align__(16) float g_WihT[H_*1200];
__device__ __align__(16) float g_WhhT[H_*1200];
__device__ __align__(16) float g_rWihT[H_*H_];
__device__ __align__(16) float g_rWhhT[H_*H_];
__device__ __align__(16) float g_fc1T[600*600];
__device__ __align__(16) float g_fc2T[600*OUT_];
__device__ __align__(16) float g_WpT[300*2400];
__device__ __align__(16) float g_WeT[300*300];
__device__ int g_count[B_];

__device__ __align__(16) __nv_bfloat16 g_nAh[(size_t)N_*KPN];
__device__ __align__(16) __nv_bfloat16 g_nAl[(size_t)N_*KPN];
__device__ __align__(16) __nv_bfloat16 g_eAh[(size_t)E_*KPE];
__device__ __align__(16) __nv_bfloat16 g_eAl[(size_t)E_*KPE];
__device__ __align__(16) __nv_bfloat16 g_nBh[(size_t)B_*NP*KPN];
__device__ __align__(16) __nv_bfloat16 g_nBl[(size_t)B_*NP*KPN];
__device__ __align__(16) __nv_bfloat16 g_eBh[(size_t)B_*NP*KPE];
__device__ __align__(16) __nv_bfloat16 g_eBl[(size_t)B_*NP*KPE];

__device__ __forceinline__ float sigm(float x){ return 1.f/(1.f+expf(-x)); }
__device__ __forceinline__ float eluf(float x){ return x>0.f ? x : expm1f(x); }

__device__ __forceinline__ uint32_t smem_u32(const void* p){
    uint32_t a;
    asm("{ .reg .u64 t; cvta.to.shared.u64 t, %1; cvt.u32.u64 %0, t; }" : "=r"(a) : "l"(p));
    return a;
}
__device__ __forceinline__ void mma_bf16(float* c, const uint32_t* a, const uint32_t* b){
    asm volatile("mma.sync.aligned.m16n8k16.row.col.f32.bf16.bf16.f32 "
        "{%0,%1,%2,%3}, {%4,%5,%6,%7}, {%8,%9}, {%0,%1,%2,%3};"
        : "+f"(c[0]),"+f"(c[1]),"+f"(c[2]),"+f"(c[3])
        : "r"(a[0]),"r"(a[1]),"r"(a[2]),"r"(a[3]), "r"(b[0]),"r"(b[1]));
}
__device__ __forceinline__ void ldsm4(uint32_t* r, uint32_t addr){
    asm volatile("ldmatrix.sync.aligned.m8n8.x4.shared.b16 {%0,%1,%2,%3}, [%4];"
        : "=r"(r[0]),"=r"(r[1]),"=r"(r[2]),"=r"(r[3]) : "r"(addr));
}
__device__ __forceinline__ void ldsm2(uint32_t* r, uint32_t addr){
    asm volatile("ldmatrix.sync.aligned.m8n8.x2.shared.b16 {%0,%1}, [%2];"
        : "=r"(r[0]),"=r"(r[1]) : "r"(addr));
}
__device__ __forceinline__ void cpa16(uint32_t dst, const void* src){
    asm volatile("cp.async.cg.shared.global [%0], [%1], 16;" :: "r"(dst), "l"(src) : "memory");
}
__device__ __forceinline__ void cpa_commit(){
    asm volatile("cp.async.commit_group;" ::: "memory");
}
template<int Nw>
__device__ __forceinline__ void cpa_wait(){
    asm volatile("cp.async.wait_group %0;" :: "n"(Nw) : "memory");
}

// ---------------- pipelined bf16-split mma GEMM ----------------
// CTA: 64 rows x 320 cols, 8 warps (warp wq -> cols [wq*40, wq*40+40)).
// K in 32-chunks, cp.async double-buffered. smem row stride 40 bf16 (80B).
// NODE=1 -> dotns[row] = s; NODE=0 -> atomicAdd(dotnr[dst], dist[src]*s).
#define SMS 40
#define BUF_BYTES 61440
#define O_BH 0
#define O_BL 25600
#define O_AH 51200
#define O_AL 56320
#define O_W  122880
#define O_ROW 124160
#define DYN_MMA 124416

template<int NODE>
__global__ void __launch_bounds__(256)
gemm_mma2_k(const __nv_bfloat16* __restrict__ Ah, const __nv_bfloat16* __restrict__ Al,
            const __nv_bfloat16* __restrict__ Bh, const __nv_bfloat16* __restrict__ Bl,
            const int* __restrict__ bidx, const float* __restrict__ wvec,
            float* __restrict__ outNS, float* __restrict__ outNR,
            const int* __restrict__ srcI, const int* __restrict__ dstI,
            const float* __restrict__ distP)
{
    constexpr int KP  = NODE ? KPN : KPE;
    constexpr int NCH = KP/32;
    extern __shared__ char smem[];
    const uint32_t sb = smem_u32(smem);
    const int tid = threadIdx.x;
    const int wq  = tid>>5, lane = tid&31;
    const int row0 = blockIdx.x * 64;
    const int b = bidx[row0];

    float* sw   = (float*)(smem + O_W);
    float* srow = (float*)(smem + O_ROW);
    for (int j=tid; j<NP; j+=256) sw[j] = (j<300) ? wvec[j] : 0.f;
    if (tid<64) srow[tid] = 0.f;

    const __nv_bfloat16* Ahp = Ah + (size_t)row0*KP;
    const __nv_bfloat16* Alp = Al + (size_t)row0*KP;
    const __nv_bfloat16* Bhp = Bh + (size_t)b*NP*KP;
    const __nv_bfloat16* Blp = Bl + (size_t)b*NP*KP;

    // per-thread load coordinates
    const int ar = tid>>2, aq = tid&3;          // A: 64 rows x 4 quads
    const uint32_t aDst = (uint32_t)(ar*(SMS*2) + aq*16);
    const size_t   aSrc = (size_t)ar*KP + aq*8;

    float acc[4][5][4];
    #pragma unroll
    for(int m=0;m<4;m++){
        #pragma unroll
        for(int t=0;t<5;t++){
            #pragma unroll
            for(int q=0;q<4;q++) acc[m][t][q]=0.f;
        }
    }

    // ---- issue chunk-0 loads ----
    {
        uint32_t bb = sb;
        cpa16(bb + O_AH + aDst, Ahp + aSrc);
        cpa16(bb + O_AL + aDst, Alp + aSrc);
        for (int i=tid; i<1280; i+=256){
            int r = i>>2, q = i&3;
            uint32_t d = (uint32_t)(r*(SMS*2) + q*16);
            size_t s = (size_t)r*KP + q*8;
            cpa16(bb + O_BH + d, Bhp + s);
            cpa16(bb + O_BL + d, Blp + s);
        }
        cpa_commit();
    }

    const uint32_t aRow = (uint32_t)(lane & 15);
    const uint32_t aHalf = (uint32_t)((lane >> 4) & 1) * 16u;
    const uint32_t bRow = (uint32_t)(lane & 7);
    const uint32_t bHalf = (uint32_t)((lane >> 3) & 1) * 16u;

    for (int kc=0; kc<NCH; kc++){
        if (kc+1 < NCH){
            uint32_t bb = sb + ((kc+1)&1)*BUF_BYTES;
            size_t ko = (size_t)(kc+1)*32;
            cpa16(bb + O_AH + aDst, Ahp + aSrc + ko);
            cpa16(bb + O_AL + aDst, Alp + aSrc + ko);
            for (int i=tid; i<1280; i+=256){
                int r = i>>2, q = i&3;
                uint32_t d = (uint32_t)(r*(SMS*2) + q*16);
                size_t s = (size_t)r*KP + q*8 + ko;
                cpa16(bb + O_BH + d, Bhp + s);
                cpa16(bb + O_BL + d, Blp + s);
            }
            cpa_commit();
            cpa_wait<1>();
        } else {
            cpa_wait<0>();
        }
        __syncthreads();

        const uint32_t cb = sb + (kc&1)*BUF_BYTES;
        #pragma unroll
        for (int kb=0; kb<2; kb++){
            uint32_t ah[4][4], al[4][4];
            #pragma unroll
            for (int m=0;m<4;m++){
                uint32_t off = (uint32_t)((m*16 + aRow)*(SMS*2)) + (uint32_t)kb*32 + aHalf;
                ldsm4(ah[m], cb + O_AH + off);
                ldsm4(al[m], cb + O_AL + off);
            }
            #pragma unroll
            for (int t=0;t<5;t++){
                uint32_t bh[2], bl[2];
                uint32_t off = (uint32_t)((wq*40 + t*8 + bRow)*(SMS*2)) + (uint32_t)kb*32 + bHalf;
                ldsm2(bh, cb + O_BH + off);
                ldsm2(bl, cb + O_BL + off);
                #pragma unroll
                for (int m=0;m<4;m++){
                    mma_bf16(acc[m][t], ah[m], bh);
                    mma_bf16(acc[m][t], ah[m], bl);
                    mma_bf16(acc[m][t], al[m], bh);
                }
            }
        }
        __syncthreads();
    }

    // epilogue: elu * w, reduce per-row
    #pragma unroll
    for (int m=0;m<4;m++){
        float sl=0.f, sh=0.f;
        #pragma unroll
        for (int t=0;t<5;t++){
            int j0 = wq*40 + t*8 + (lane&3)*2;
            float w0=sw[j0], w1=sw[j0+1];
            float c0=acc[m][t][0], c1=acc[m][t][1], c2=acc[m][t][2], c3=acc[m][t][3];
            c0 = c0>0.f?c0:expm1f(c0); c1 = c1>0.f?c1:expm1f(c1);
            c2 = c2>0.f?c2:expm1f(c2); c3 = c3>0.f?c3:expm1f(c3);
            sl += c0*w0 + c1*w1;
            sh += c2*w0 + c3*w1;
        }
        sl += __shfl_xor_sync(0xffffffffu, sl, 1);
        sl += __shfl_xor_sync(0xffffffffu, sl, 2);
        sh += __shfl_xor_sync(0xffffffffu, sh, 1);
        sh += __shfl_xor_sync(0xffffffffu, sh, 2);
        if ((lane&3)==0){
            int r = m*16 + (lane>>2);
            atomicAdd(&srow[r],   sl);
            atomicAdd(&srow[r+8], sh);
        }
    }
    __syncthreads();
    if (tid<64){
        int r = row0 + tid;
        float s = srow[tid];
        if (NODE) outNS[r] = s;
        else      atomicAdd(&outNR[dstI[r]], distP[srcI[r]]*s);
    }
}

// ---------------- split / build kernels ----------------
__global__ void zeroinstr_k(){
    int idx = blockIdx.x*blockDim.x + threadIdx.x;
    if (idx < B_*4*H_) g_instr[idx]=0.f;
    if (idx < B_*P_)   g_npsim[idx]=0.f;
}
__global__ void splitN_k(const float* __restrict__ attrs){
    size_t idx = (size_t)blockIdx.x*blockDim.x + threadIdx.x;
    if (idx < (size_t)N_*KPN){
        int k = (int)(idx % KPN);
        size_t row = idx / KPN;
        float v = (k < 2400) ? attrs[row*2400 + k] : 0.f;
        __nv_bfloat16 hi = __float2bfloat16_rn(v);
        g_nAh[idx] = hi;
        g_nAl[idx] = __float2bfloat16_rn(v - __bfloat162float(hi));
    }
}
__global__ void splitE_k(const float* __restrict__ eattrs){
    size_t idx = (size_t)blockIdx.x*blockDim.x + threadIdx.x;
    if (idx < (size_t)E_*KPE){
        int k = (int)(idx % KPE);
        size_t row = idx / KPE;
        float v = (k < 300) ? eattrs[row*300 + k] : 0.f;
        __nv_bfloat16 hi = __float2bfloat16_rn(v);
        g_eAh[idx] = hi;
        g_eAl[idx] = __float2bfloat16_rn(v - __bfloat162float(hi));
    }
}
__global__ void wpT_k(const float* __restrict__ Wp){
    int idx = blockIdx.x*blockDim.x + threadIdx.x;
    if (idx < 300*2400){
        int j = idx / 2400, ph = idx % 2400;
        g_WpT[idx] = Wp[(size_t)ph*300 + j];
    }
}
__global__ void weT_k(const float* __restrict__ We){
    int idx = blockIdx.x*blockDim.x + threadIdx.x;
    if (idx < 300*300){
        int j = idx / 300, k = idx % 300;
        g_WeT[idx] = We[k*300 + j];
    }
}
__global__ void bnode_k(int step){
    size_t idx = (size_t)blockIdx.x*blockDim.x + threadIdx.x;
    if (idx < (size_t)B_*NP*KPN){
        int b = (int)(idx / ((size_t)NP*KPN));
        int r = (int)(idx % ((size_t)NP*KPN));
        int j = r / KPN, k = r % KPN;
        float v = 0.f;
        if (j < 300 && k < 2400){
            int p = k / 300, h = k - p*300;
            v = g_WpT[(size_t)j*2400 + k] * g_npsim[b*8+p] * g_instr[(size_t)b*1200 + step*300 + h];
        }
        __nv_bfloat16 hi = __float2bfloat16_rn(v);
        g_nBh[idx] = hi;
        g_nBl[idx] = __float2bfloat16_rn(v - __bfloat162float(hi));
    }
}
__global__ void bedge_k(int step){
    int idx = blockIdx.x*blockDim.x + threadIdx.x;
    if (idx < B_*NP*KPE){
        int b = idx / (NP*KPE);
        int r = idx % (NP*KPE);
        int j = r / KPE, k = r % KPE;
        float v = 0.f;
        if (j < 300 && k < 300)
            v = g_WeT[j*300 + k] * g_instr[(size_t)b*1200 + step*300 + k];
        __nv_bfloat16 hi = __float2bfloat16_rn(v);
        g_eBh[idx] = hi;
        g_eBl[idx] = __float2bfloat16_rn(v - __bfloat162float(hi));
    }
}

// ---------------- fp32 SGEMM for small GEMMs ----------------
template<bool ACC>
__global__ void __launch_bounds__(256)
sgemm_k(const float* __restrict__ A, int lda,
        const float* __restrict__ Bm, int ldb,
        float* __restrict__ Cm, int ldc, int Nc, int K)
{
    __shared__ __align__(16) float As[8][128];
    __shared__ __align__(16) float Bs[8][128];
    const int tid = threadIdx.x;
    const int row0 = blockIdx.y * 128, col0 = blockIdx.x * 128;
    const int tx = tid & 15, ty = tid >> 4;

    float acc[8][8];
    #pragma unroll
    for(int i=0;i<8;i++){
        #pragma unroll
        for(int j=0;j<8;j++) acc[i][j]=0.f;
    }
    const int arow = tid>>1, akq = (tid&1)*4;
    const int brow = tid>>5, bc4 = (tid&31)*4;

    for (int k0=0; k0<K; k0+=8){
        float4 av = make_float4(0.f,0.f,0.f,0.f);
        if (k0 + akq < K)
            av = *reinterpret_cast<const float4*>(A + (size_t)(row0+arow)*lda + k0 + akq);
        float4 bv = make_float4(0.f,0.f,0.f,0.f);
        int krow = k0 + brow;
        if (krow < K){
            int c = col0 + bc4;
            const float* bp = Bm + (size_t)krow*ldb;
            if (c + 3 < Nc) bv = *reinterpret_cast<const float4*>(bp + c);
            else {
                if (c  <Nc) bv.x = bp[c];
                if (c+1<Nc) bv.y = bp[c+1];
                if (c+2<Nc) bv.z = bp[c+2];
                if (c+3<Nc) bv.w = bp[c+3];
            }
        }
        __syncthreads();
        As[akq+0][arow]=av.x; As[akq+1][arow]=av.y;
        As[akq+2][arow]=av.z; As[akq+3][arow]=av.w;
        *reinterpret_cast<float4*>(&Bs[brow][bc4]) = bv;
        __syncthreads();
        #pragma unroll
        for (int kk=0;kk<8;kk++){
            float ra[8], rb[8];
            #pragma unroll
            for(int i=0;i<8;i++) ra[i]=As[kk][ty+16*i];
            #pragma unroll
            for(int j=0;j<8;j++) rb[j]=Bs[kk][tx+16*j];
            #pragma unroll
            for(int i=0;i<8;i++){
                #pragma unroll
                for(int j=0;j<8;j++) acc[i][j] += ra[i]*rb[j];
            }
        }
    }
    #pragma unroll
    for(int i=0;i<8;i++){
        int r = row0 + ty + 16*i;
        #pragma unroll
        for(int j=0;j<8;j++){
            int c = col0 + tx + 16*j;
            if (c < Nc){
                size_t idx = (size_t)r*ldc + c;
                Cm[idx] = ACC ? (Cm[idx] + acc[i][j]) : acc[i][j];
            }
        }
    }
}

// ---------------- small kernels ----------------
__global__ void transpose_k(const float* __restrict__ src, float* __restrict__ dst, int R, int Cc){
    int idx = blockIdx.x*blockDim.x + threadIdx.x;
    if (idx < R*Cc){ int r=idx/Cc, c=idx-r*Cc; dst[(size_t)c*R + r] = src[idx]; }
}
__global__ void vextT_k(const float* __restrict__ cv, const float* __restrict__ demb){
    int idx = blockIdx.x*blockDim.x + threadIdx.x;
    if (idx < H_*LDSIM){
        int h = idx / LDSIM, c = idx - h*LDSIM;
        float v = 0.f;
        if (c < C_) v = cv[(size_t)c*H_ + h];
        else if (c == C_) v = demb[h];
        g_vextT[idx] = v;
    }
}
__global__ void __launch_bounds__(256) smrow_k(){
    __shared__ float red[256];
    int r = blockIdx.x, t = threadIdx.x;
    float* row = g_sim + (size_t)r*LDSIM;
    float mx = -1e30f;
    for(int c=t;c<2049;c+=256) mx = fmaxf(mx, row[c]);
    red[t]=mx; __syncthreads();
    for(int s=128;s>0;s>>=1){ if(t<s) red[t]=fmaxf(red[t],red[t+s]); __syncthreads(); }
    mx = red[0]; __syncthreads();
    float sm = 0.f;
    for(int c=t;c<2049;c+=256){ float e=expf(row[c]-mx); row[c]=e; sm+=e; }
    red[t]=sm; __syncthreads();
    for(int s=128;s>0;s>>=1){ if(t<s) red[t]+=red[t+s]; __syncthreads(); }
    float inv = 1.f/red[0]; __syncthreads();
    for(int c=t;c<2049;c+=256) row[c]*=inv;
}
__global__ void tagged_init_k(const float* __restrict__ q){
    int idx = blockIdx.x*blockDim.x + threadIdx.x;
    if (idx < B_*L_*H_){
        int r = idx / H_;
        g_tagged[idx] = g_sim[(size_t)r*LDSIM + C_] * q[idx];
    }
}
__global__ void __launch_bounds__(320) lstm_k(const float* __restrict__ bih, const float* __restrict__ bhh){
    __shared__ float h_s[304], c_s[304], z_s[1200];
    int b = blockIdx.x, tid = threadIdx.x;
    if (tid<300){ h_s[tid]=0.f; c_s[tid]=0.f; }
    __syncthreads();
    const float4* W = reinterpret_cast<const float4*>(g_WhhT);
    for (int t=0;t<20;t++){
        if (tid<300){
            int j4 = tid*4;
            float4 a = *reinterpret_cast<const float4*>(&g_Zx[((size_t)b*20+t)*1200 + j4]);
            a.x += bih[j4]+bhh[j4];     a.y += bih[j4+1]+bhh[j4+1];
            a.z += bih[j4+2]+bhh[j4+2]; a.w += bih[j4+3]+bhh[j4+3];
            for(int h=0;h<300;h++){
                float hv = h_s[h];
                float4 w = W[(size_t)h*300 + tid];
                a.x += hv*w.x; a.y += hv*w.y; a.z += hv*w.z; a.w += hv*w.w;
            }
            *reinterpret_cast<float4*>(&z_s[j4]) = a;
        }
        __syncthreads();
        if (tid<300){
            float iv=sigm(z_s[tid]), fv=sigm(z_s[300+tid]);
            float gv=tanhf(z_s[600+tid]), ov=sigm(z_s[900+tid]);
            float c = fv*c_s[tid] + iv*gv;
            c_s[tid]=c; h_s[tid]=ov*tanhf(c);
        }
        __syncthreads();
    }
    if (tid<300) g_h[b*300+tid] = h_s[tid];
}
__global__ void __launch_bounds__(320) rnn_k(const float* __restrict__ rbih, const float* __restrict__ rbhh){
    __shared__ float enc[304], ex[304], hx[304], hn[304];
    int b = blockIdx.x, tid = threadIdx.x;
    if (tid<300) enc[tid]=g_h[b*300+tid];
    __syncthreads();
    if (tid<300){
        float a = rbih[tid]+rbhh[tid];
        for(int k=0;k<300;k++) a += enc[k]*g_rWihT[k*300+tid];
        ex[tid]=a; hx[tid]=0.f;
    }
    __syncthreads();
    for(int it=0; it<4; it++){
        if (tid<300){
            float a = ex[tid];
            for(int k=0;k<300;k++) a += hx[k]*g_rWhhT[k*300+tid];
            a = a>0.f ? a : 0.f;
            hn[tid]=a;
            g_hidden[(size_t)b*1200 + it*300 + tid] = a;
        }
        __syncthreads();
        if (tid<300) hx[tid]=hn[tid];
        __syncthreads();
    }
}
__global__ void __launch_bounds__(256) attn_k(){
    __shared__ float hid[1200], tg[6000], at[80];
    int b = blockIdx.x, tid = threadIdx.x;
    for(int j=tid;j<1200;j+=256) hid[j]=g_hidden[(size_t)b*1200+j];
    for(int j=tid;j<6000;j+=256) tg[j]=g_tagged[(size_t)b*6000+j];
    __syncthreads();
    if (tid<80){
        int i=tid/20, l=tid%20;
        float a=0.f;
        for(int h=0;h<300;h++) a += hid[i*300+h]*tg[l*300+h];
        at[tid]=a;
    }
    __syncthreads();
    if (tid<4){
        float mx=-1e30f;
        for(int l=0;l<20;l++) mx=fmaxf(mx,at[tid*20+l]);
        float s=0.f;
        for(int l=0;l<20;l++){ float e=expf(at[tid*20+l]-mx); at[tid*20+l]=e; s+=e; }
        float inv=1.f/s;
        for(int l=0;l<20;l++) at[tid*20+l]*=inv;
    }
    __syncthreads();
    for(int idx=tid; idx<1200; idx+=256){
        int i=idx/300, h=idx-i*300;
        float a=0.f;
        for(int l=0;l<20;l++) a += at[i*20+l]*tg[l*300+h];
        g_instr[(size_t)b*1200+idx]=a;
    }
}
__global__ void psim_k(const float* __restrict__ pe, int step){
    __shared__ float lg[64][9];
    int tid = threadIdx.x;
    if (tid < 576){
        int b=tid/9, j=tid-b*9;
        const float* ip = g_instr + (size_t)b*1200 + step*300;
        float a=0.f;
        for(int h=0;h<300;h++) a += ip[h]*pe[j*300+h];
        lg[b][j]=a;
    }
    __syncthreads();
    if (tid < 64){
        float mx=-1e30f;
        for(int j=0;j<9;j++) mx=fmaxf(mx,lg[tid][j]);
        float e[9], s=0.f;
        for(int j=0;j<9;j++){ e[j]=expf(lg[tid][j]-mx); s+=e[j]; }
        float inv=1.f/s;
        for(int p=0;p<8;p++) g_npsim[tid*8+p]=e[p]*inv;
        g_rsim[tid]=e[8]*inv;
    }
}
__global__ void zero_misc_k(){
    int idx = blockIdx.x*blockDim.x + threadIdx.x;
    if (idx < B_) g_count[idx]=0;
    if (idx < B_*H_) g_agg[idx]=0.f;
}
__global__ void count_k(const int* __restrict__ ni){
    int n = blockIdx.x*blockDim.x + threadIdx.x;
    if (n < N_) atomicAdd(&g_count[ni[n]], 1);
}
__global__ void distinit_k(const int* __restrict__ ni){
    int n = blockIdx.x*blockDim.x + threadIdx.x;
    if (n < N_) g_dist[n] = 1.f/(float)g_count[ni[n]];
}
__global__ void zerodots_k(){
    int n = blockIdx.x*blockDim.x + threadIdx.x;
    if (n < N_){ g_dotns[n]=0.f; g_dotnr[n]=0.f; }
}
__global__ void __launch_bounds__(512) segsm_k(){
    __shared__ float red[512];
    int b = blockIdx.x, t = threadIdx.x;
    int n = b*512 + t;
    float v1 = g_dotns[n], v2 = g_dotnr[n];
    red[t]=v1; __syncthreads();
    for(int s=256;s>0;s>>=1){ if(t<s) red[t]=fmaxf(red[t],red[t+s]); __syncthreads(); }
    float m1=red[0]; __syncthreads();
    float e1=expf(v1-m1);
    red[t]=e1; __syncthreads();
    for(int s=256;s>0;s>>=1){ if(t<s) red[t]+=red[t+s]; __syncthreads(); }
    float s1=red[0]; __syncthreads();
    red[t]=v2; __syncthreads();
    for(int s=256;s>0;s>>=1){ if(t<s) red[t]=fmaxf(red[t],red[t+s]); __syncthreads(); }
    float m2=red[0]; __syncthreads();
    float e2=expf(v2-m2);
    red[t]=e2; __syncthreads();
    for(int s=256;s>0;s>>=1){ if(t<s) red[t]+=red[t+s]; __syncthreads(); }
    float s2=red[0];
    float rs = g_rsim[b];
    g_dist[n] = rs*(e2/s2) + (1.f-rs)*(e1/s1);
}
__global__ void __launch_bounds__(320) agg_k(const float* __restrict__ attrs, const int* __restrict__ ni){
    __shared__ float np_s[8], d_s[64];
    int blk = blockIdx.x, tid = threadIdx.x;
    int n0 = blk*64;
    int b = ni[n0];
    if (tid<8)  np_s[tid] = g_npsim[b*8+tid];
    if (tid<64) d_s[tid]  = g_dist[n0+tid];
    __syncthreads();
    if (tid<300){
        float acc = 0.f;
        for(int n=0;n<64;n++){
            const float* ap = attrs + (size_t)(n0+n)*2400 + tid;
            float s = 0.f;
            #pragma unroll
            for(int p=0;p<8;p++) s += np_s[p]*ap[p*300];
            acc += d_s[n]*s;
        }
        atomicAdd(&g_agg[b*300+tid], acc);
    }
}
__global__ void __launch_bounds__(256) fc_k(const float* __restrict__ fc1b,
                                            const float* __restrict__ fc2b,
                                            float* __restrict__ out){
    __shared__ float ft[600], h1[600];
    int b = blockIdx.x, tid = threadIdx.x;
    for(int j=tid;j<300;j+=256){ ft[j]=g_h[b*300+j]; ft[300+j]=g_agg[b*300+j]; }
    __syncthreads();
    for(int j=tid;j<600;j+=256){
        float a = fc1b[j];
        for(int k=0;k<600;k++) a += ft[k]*g_fc1T[k*600+j];
        h1[j] = eluf(a);
    }
    __syncthreads();
    for(int o=tid;o<OUT_;o+=256){
        float a = fc2b[o];
        for(int k=0;k<600;k++) a += h1[k]*g_fc2T[(size_t)k*OUT_+o];
        out[(size_t)b*OUT_+o]=a;
    }
}

// ---------------- driver ----------------
extern "C" void kernel_launch(void* const* d_in, const int* in_sizes, int n_in,
                              void* d_out, int out_size) {
    const float* questions = (const float*)d_in[0];
    const float* cv        = (const float*)d_in[1];
    const float* pe        = (const float*)d_in[2];
    const float* attrs     = (const float*)d_in[3];
    const float* eattrs    = (const float*)d_in[4];
    const float* wtag      = (const float*)d_in[5];
    const float* demb      = (const float*)d_in[6];
    const float* lWih      = (const float*)d_in[7];
    const float* lWhh      = (const float*)d_in[8];
    const float* lbih      = (const float*)d_in[9];
    const float* lbhh      = (const float*)d_in[10];
    const float* rWih      = (const float*)d_in[11];
    const float* rWhh      = (const float*)d_in[12];
    const float* rbih      = (const float*)d_in[13];
    const float* rbhh      = (const float*)d_in[14];
    const float* Wp        = (const float*)d_in[15];
    const float* We        = (const float*)d_in[16];
    const float* w_ns      = (const float*)d_in[17];
    const float* w_rs      = (const float*)d_in[18];
    const float* fc1w      = (const float*)d_in[19];
    const float* fc1b      = (const float*)d_in[20];
    const float* fc2w      = (const float*)d_in[21];
    const float* fc2b      = (const float*)d_in[22];
    const int*   ni        = (const int*)d_in[23];
    const int*   esrc      = (const int*)d_in[24];
    const int*   edst      = (const int*)d_in[25];
    const int*   ebatch    = (const int*)d_in[26];
    float* out = (float*)d_out;

    float *WihT, *WhhT, *rWihT, *rWhhT, *fc1T, *fc2T;
    float *qt, *sim, *vextT, *tagged, *Zx;
    float *dotns, *dotnr, *distP;
    __nv_bfloat16 *nAh,*nAl,*eAh,*eAl,*nBh,*nBl,*eBh,*eBl;
    cudaGetSymbolAddress((void**)&WihT,  g_WihT);
    cudaGetSymbolAddress((void**)&WhhT,  g_WhhT);
    cudaGetSymbolAddress((void**)&rWihT, g_rWihT);
    cudaGetSymbolAddress((void**)&rWhhT, g_rWhhT);
    cudaGetSymbolAddress((void**)&fc1T,  g_fc1T);
    cudaGetSymbolAddress((void**)&fc2T,  g_fc2T);
    cudaGetSymbolAddress((void**)&qt,    g_qt);
    cudaGetSymbolAddress((void**)&sim,   g_sim);
    cudaGetSymbolAddress((void**)&vextT, g_vextT);
    cudaGetSymbolAddress((void**)&tagged,g_tagged);
    cudaGetSymbolAddress((void**)&Zx,    g_Zx);
    cudaGetSymbolAddress((void**)&dotns, g_dotns);
    cudaGetSymbolAddress((void**)&dotnr, g_dotnr);
    cudaGetSymbolAddress((void**)&distP, g_dist);
    cudaGetSymbolAddress((void**)&nAh, g_nAh);
    cudaGetSymbolAddress((void**)&nAl, g_nAl);
    cudaGetSymbolAddress((void**)&eAh, g_eAh);
    cudaGetSymbolAddress((void**)&eAl, g_eAl);
    cudaGetSymbolAddress((void**)&nBh, g_nBh);
    cudaGetSymbolAddress((void**)&nBl, g_nBl);
    cudaGetSymbolAddress((void**)&eBh, g_eBh);
    cudaGetSymbolAddress((void**)&eBl, g_eBl);

    cudaFuncSetAttribute(gemm_mma2_k<1>, cudaFuncAttributeMaxDynamicSharedMemorySize, DYN_MMA);
    cudaFuncSetAttribute(gemm_mma2_k<0>, cudaFuncAttributeMaxDynamicSharedMemorySize, DYN_MMA);

    // ---- probe prologue: launches #0-#4, then #5 = real edge-mma (small grid) for ncu ----
    weT_k<<<CDIV(300*300,256),256>>>(We);                                   // #0
    zeroinstr_k<<<CDIV(B_*4*H_,256),256>>>();                               // #1
    splitE_k<<<(int)CDIV((size_t)E_*KPE,256),256>>>(eattrs);                // #2
    bedge_k<<<CDIV(B_*NP*KPE,256),256>>>(0);                                // #3 (zero B)
    splitN_k<<<(int)CDIV((size_t)N_*KPN,256),256>>>(attrs);                 // #4
    gemm_mma2_k<0><<<256,256,DYN_MMA>>>(eAh,eAl,eBh,eBl, ebatch, w_rs,      // #5 PROBE
        0, dotnr, esrc, edst, distP);

    // one-time prep
    transpose_k<<<CDIV(1200*300,256),256>>>(lWih, WihT, 1200, 300);
    transpose_k<<<CDIV(1200*300,256),256>>>(lWhh, WhhT, 1200, 300);
    transpose_k<<<CDIV(300*300,256),256>>>(rWih, rWihT, 300, 300);
    transpose_k<<<CDIV(300*300,256),256>>>(rWhh, rWhhT, 300, 300);
    transpose_k<<<CDIV(600*600,256),256>>>(fc1w, fc1T, 600, 600);
    transpose_k<<<CDIV(OUT_*600,256),256>>>(fc2w, fc2T, OUT_, 600);
    vextT_k<<<CDIV(H_*LDSIM,256),256>>>(cv, demb);
    zero_misc_k<<<CDIV(B_*H_,256),256>>>();
    count_k<<<CDIV(N_,256),256>>>(ni);
    distinit_k<<<CDIV(N_,256),256>>>(ni);
    wpT_k<<<CDIV(300*2400,256),256>>>(Wp);

    // tagging
    sgemm_k<false><<<dim3(CDIV(300,128),10),256>>>(questions,300, wtag,300, qt,300, 300,300);
    sgemm_k<false><<<dim3(CDIV(2049,128),10),256>>>(qt,300, vextT,LDSIM, sim,LDSIM, 2049,300);
    smrow_k<<<B_*L_,256>>>();
    tagged_init_k<<<CDIV(B_*L_*H_,256),256>>>(questions);
    sgemm_k<true><<<dim3(CDIV(300,128),10),256>>>(sim,LDSIM, cv,300, tagged,300, 300,2048);

    // LSTM + RNN + attn
    sgemm_k<false><<<dim3(CDIV(1200,128),10),256>>>(tagged,300, WihT,1200, Zx,1200, 1200,300);
    lstm_k<<<B_,320>>>(lbih, lbhh);
    rnn_k<<<B_,320>>>(rbih, rbhh);
    attn_k<<<B_,256>>>();

    // reasoning steps
    for (int step=0; step<3; step++){
        psim_k<<<1,576>>>(pe, step);
        bnode_k<<<(int)CDIV((size_t)B_*NP*KPN,256),256>>>(step);
        bedge_k<<<CDIV(B_*NP*KPE,256),256>>>(step);
        zerodots_k<<<CDIV(N_,256),256>>>();
        gemm_mma2_k<1><<<N_/64,256,DYN_MMA>>>(nAh,nAl,nBh,nBl, ni, w_ns, dotns, 0, 0,0,0);
        gemm_mma2_k<0><<<E_/64,256,DYN_MMA>>>(eAh,eAl,eBh,eBl, ebatch, w_rs, 0, dotnr, esrc, edst, distP);
        segsm_k<<<B_,512>>>();
    }

    // final aggregation + MLP
    psim_k<<<1,576>>>(pe, 3);
    agg_k<<<N_/64,320>>>(attrs, ni);
    fc_k<<<B_,256>>>(fc1b, fc2b, out);
}